// round 9
// baseline (speedup 1.0000x reference)
#include <cuda_runtime.h>
#include <cuda_bf16.h>
#include <math.h>
#include <stddef.h>

// Problem constants
#define VOCAB 32000
#define HDIM  1024
#define KDIM  512
#define VDIM  1024
#define ODIM  1024
#define NLAYER 2
#define BATCH 4
#define TSEQ  1024
#define NTOK  (BATCH * TSEQ)   // 4096

// ---------------------------------------------------------------------------
// Scratch buffers (device globals — allocation-free per harness rules)
// ---------------------------------------------------------------------------
__device__ float g_h[NTOK * HDIM];      // 16 MB : layer input/output (hidden)
__device__ float g_q[NTOK * KDIM];      //  8 MB
__device__ float g_k[NTOK * KDIM];      //  8 MB
__device__ float g_g[NTOK * KDIM];      //  8 MB
__device__ float g_v[NTOK * VDIM];      // 16 MB
__device__ float g_attn[NTOK * VDIM];   // 16 MB : scan output (pre-Wo)

// ---------------------------------------------------------------------------
// Embedding gather
// ---------------------------------------------------------------------------
__global__ void embed_kernel(const int* __restrict__ ids,
                             const float* __restrict__ emb,
                             float* __restrict__ h)
{
    int tok = blockIdx.x;
    int id  = ids[tok];
    const float4* src = (const float4*)(emb + (size_t)id * HDIM);
    float4* dst       = (float4*)(h + (size_t)tok * HDIM);
    dst[threadIdx.x] = src[threadIdx.x];     // 256 thr * float4 = HDIM
}

// ---------------------------------------------------------------------------
// TF32 tensor-core GEMM with 3xTF32 accuracy recovery.
//   C[M,N] = A[M,K] @ B[K,N] + bias[N]   (optional sigmoid)
// A = A_hi + A_lo (tf32 splits); acc += Ah*Bh + Al*Bh + Ah*Bl  -> ~fp32 accuracy.
// Tiles: 128x128x8, 256 threads, 8 warps (2x4), warp tile 64x32 = 4x4 m16n8k8.
// Double-buffered smem with register prefetch; one __syncthreads per k-slab.
// M=4096, N in {512,1024,32000}, K=1024 -> all divisible, no bounds checks.
// ---------------------------------------------------------------------------
__device__ __forceinline__ unsigned f2tf32(float x) {
    unsigned r;
    asm("cvt.rna.tf32.f32 %0, %1;" : "=r"(r) : "f"(x));
    return r;   // low 13 mantissa bits zeroed -> valid fp32 bit pattern
}

__device__ __forceinline__ void mma_tf32(float c[4],
                                         const unsigned a[4],
                                         const unsigned b[2]) {
    asm volatile(
        "mma.sync.aligned.m16n8k8.row.col.f32.tf32.tf32.f32 "
        "{%0,%1,%2,%3}, {%4,%5,%6,%7}, {%8,%9}, {%0,%1,%2,%3};"
        : "+f"(c[0]), "+f"(c[1]), "+f"(c[2]), "+f"(c[3])
        : "r"(a[0]), "r"(a[1]), "r"(a[2]), "r"(a[3]),
          "r"(b[0]), "r"(b[1]));
}

#define AS_STRIDE 12    // 8 cols + pad : conflict-free for frag loads (g*12+t)
#define BS_STRIDE 136   // 128 cols + pad: (136 % 32 == 8) -> t*8+g all distinct

template<int ACT>   // 0 = none, 1 = sigmoid
__global__ __launch_bounds__(256)
void tf32_gemm_kernel(const float* __restrict__ A,
                      const float* __restrict__ B,
                      const float* __restrict__ bias,
                      float* __restrict__ C,
                      int M, int N, int K)
{
    __shared__ unsigned Ah[2][128 * AS_STRIDE], Al[2][128 * AS_STRIDE];
    __shared__ unsigned Bh[2][8 * BS_STRIDE],  Bl[2][8 * BS_STRIDE];

    const int tid  = threadIdx.x;
    const int bx   = blockIdx.x;          // along N
    const int by   = blockIdx.y;          // along M
    const int warp = tid >> 5;
    const int lane = tid & 31;
    const int grp  = lane >> 2;           // 0..7
    const int tig  = lane & 3;            // 0..3
    const int wm   = (warp >> 2) * 64;    // warp M offset: 0 / 64
    const int wn   = (warp & 3) * 32;     // warp N offset: 0/32/64/96

    const float* Ab = A + (size_t)by * 128 * K;
    const float* Bb = B + (size_t)bx * 128;

    // global->smem mapping
    const int aRow = tid >> 1;            // 0..127
    const int aCol = (tid & 1) * 4;       // 0 / 4
    const int bRow = tid >> 5;            // 0..7
    const int bCol = (tid & 31) * 4;      // 0..124

    float acc[4][4][4];
    #pragma unroll
    for (int i = 0; i < 4; i++)
        #pragma unroll
        for (int j = 0; j < 4; j++)
            #pragma unroll
            for (int r = 0; r < 4; r++) acc[i][j][r] = 0.0f;

    // ---- prologue: slab 0 into buffer 0
    {
        float4 av = *(const float4*)(Ab + (size_t)aRow * K + aCol);
        float4 bv = *(const float4*)(Bb + (size_t)bRow * N + bCol);
        const float* af = &av.x;
        const float* bf = &bv.x;
        #pragma unroll
        for (int j = 0; j < 4; j++) {
            unsigned hi = f2tf32(af[j]);
            Ah[0][aRow * AS_STRIDE + aCol + j] = hi;
            Al[0][aRow * AS_STRIDE + aCol + j] =
                f2tf32(af[j] - __uint_as_float(hi));
            unsigned hib = f2tf32(bf[j]);
            Bh[0][bRow * BS_STRIDE + bCol + j] = hib;
            Bl[0][bRow * BS_STRIDE + bCol + j] =
                f2tf32(bf[j] - __uint_as_float(hib));
        }
    }
    __syncthreads();

    const int nIter = K >> 3;
    for (int it = 0; it < nIter; it++) {
        const int cur = it & 1;

        // prefetch next slab into registers
        float4 av, bv;
        const bool hasNext = (it + 1 < nIter);
        if (hasNext) {
            int k0 = (it + 1) << 3;
            av = *(const float4*)(Ab + (size_t)aRow * K + k0 + aCol);
            bv = *(const float4*)(Bb + (size_t)(k0 + bRow) * N + bCol);
        }

        // ---- fragments
        unsigned ah[4][4], al[4][4], bh[4][2], bl[4][2];
        #pragma unroll
        for (int mt = 0; mt < 4; mt++) {
            int base = (wm + mt * 16 + grp) * AS_STRIDE;
            ah[mt][0] = Ah[cur][base + tig];
            ah[mt][1] = Ah[cur][base + 8 * AS_STRIDE + tig];
            ah[mt][2] = Ah[cur][base + tig + 4];
            ah[mt][3] = Ah[cur][base + 8 * AS_STRIDE + tig + 4];
            al[mt][0] = Al[cur][base + tig];
            al[mt][1] = Al[cur][base + 8 * AS_STRIDE + tig];
            al[mt][2] = Al[cur][base + tig + 4];
            al[mt][3] = Al[cur][base + 8 * AS_STRIDE + tig + 4];
        }
        #pragma unroll
        for (int nt = 0; nt < 4; nt++) {
            int bb = tig * BS_STRIDE + wn + nt * 8 + grp;
            bh[nt][0] = Bh[cur][bb];
            bh[nt][1] = Bh[cur][bb + 4 * BS_STRIDE];
            bl[nt][0] = Bl[cur][bb];
            bl[nt][1] = Bl[cur][bb + 4 * BS_STRIDE];
        }

        // ---- 3xTF32 MMA
        #pragma unroll
        for (int mt = 0; mt < 4; mt++)
            #pragma unroll
            for (int nt = 0; nt < 4; nt++) {
                mma_tf32(acc[mt][nt], ah[mt], bh[nt]);
                mma_tf32(acc[mt][nt], al[mt], bh[nt]);
                mma_tf32(acc[mt][nt], ah[mt], bl[nt]);
            }

        // ---- store prefetched slab into other buffer
        if (hasNext) {
            int nxt = cur ^ 1;
            const float* af = &av.x;
            const float* bf = &bv.x;
            #pragma unroll
            for (int j = 0; j < 4; j++) {
                unsigned hi = f2tf32(af[j]);
                Ah[nxt][aRow * AS_STRIDE + aCol + j] = hi;
                Al[nxt][aRow * AS_STRIDE + aCol + j] =
                    f2tf32(af[j] - __uint_as_float(hi));
                unsigned hib = f2tf32(bf[j]);
                Bh[nxt][bRow * BS_STRIDE + bCol + j] = hib;
                Bl[nxt][bRow * BS_STRIDE + bCol + j] =
                    f2tf32(bf[j] - __uint_as_float(hib));
            }
        }
        __syncthreads();
    }

    // ---- epilogue: c0:(grp, 2t) c1:(grp, 2t+1) c2:(grp+8, 2t) c3:(grp+8, 2t+1)
    #pragma unroll
    for (int nt = 0; nt < 4; nt++) {
        int col = bx * 128 + wn + nt * 8 + tig * 2;
        float2 bs = *(const float2*)(bias + col);
        #pragma unroll
        for (int mt = 0; mt < 4; mt++) {
            int row0 = by * 128 + wm + mt * 16 + grp;
            float v0 = acc[mt][nt][0] + bs.x;
            float v1 = acc[mt][nt][1] + bs.y;
            float v2 = acc[mt][nt][2] + bs.x;
            float v3 = acc[mt][nt][3] + bs.y;
            if (ACT == 1) {
                v0 = 1.0f / (1.0f + __expf(-v0));
                v1 = 1.0f / (1.0f + __expf(-v1));
                v2 = 1.0f / (1.0f + __expf(-v2));
                v3 = 1.0f / (1.0f + __expf(-v3));
            }
            *(float2*)(C + (size_t)row0 * N + col)       = make_float2(v0, v1);
            *(float2*)(C + (size_t)(row0 + 8) * N + col) = make_float2(v2, v3);
        }
    }
}

// ---------------------------------------------------------------------------
// Gated linear-attention scan (unchanged; register-resident state).
// ---------------------------------------------------------------------------
__global__ __launch_bounds__(256)
void scan_kernel(const float* __restrict__ q,
                 const float* __restrict__ kk,
                 const float* __restrict__ gg,
                 const float* __restrict__ vv,
                 float* __restrict__ attn)
{
    const int b    = blockIdx.x >> 5;       // 0..3
    const int vblk = blockIdx.x & 31;       // 0..31
    const int v0   = vblk * 32;
    const int warp = threadIdx.x >> 5;      // 0..7
    const int lane = threadIdx.x & 31;
    const int myv  = v0 + warp * 4;         // 4 v per warp

    __shared__ float sq[KDIM];
    __shared__ float sk[KDIM];
    __shared__ float sg[KDIM];
    __shared__ float sv[32];

    float s[16][4];
    #pragma unroll
    for (int i = 0; i < 16; i++)
        #pragma unroll
        for (int j = 0; j < 4; j++) s[i][j] = 0.0f;

    const float* qb = q  + (size_t)b * TSEQ * KDIM;
    const float* kb = kk + (size_t)b * TSEQ * KDIM;
    const float* gb = gg + (size_t)b * TSEQ * KDIM;
    const float* vb = vv + (size_t)b * TSEQ * VDIM;

    for (int t = 0; t < TSEQ; t++) {
        const float* qt = qb + (size_t)t * KDIM;
        const float* kt = kb + (size_t)t * KDIM;
        const float* gt = gb + (size_t)t * KDIM;
        #pragma unroll
        for (int i = threadIdx.x; i < KDIM; i += 256) {
            sq[i] = qt[i];
            sk[i] = kt[i];
            sg[i] = gt[i];
        }
        if (threadIdx.x < 32)
            sv[threadIdx.x] = vb[(size_t)t * VDIM + v0 + threadIdx.x];
        __syncthreads();

        float vr0 = sv[warp * 4 + 0];
        float vr1 = sv[warp * 4 + 1];
        float vr2 = sv[warp * 4 + 2];
        float vr3 = sv[warp * 4 + 3];

        float a0 = 0.f, a1 = 0.f, a2 = 0.f, a3 = 0.f;
        #pragma unroll
        for (int i = 0; i < 16; i++) {
            int kidx = i * 32 + lane;
            float qv = sq[kidx];
            float kv = sk[kidx];
            float gv = sg[kidx];
            s[i][0] = s[i][0] * gv + kv * vr0;  a0 += s[i][0] * qv;
            s[i][1] = s[i][1] * gv + kv * vr1;  a1 += s[i][1] * qv;
            s[i][2] = s[i][2] * gv + kv * vr2;  a2 += s[i][2] * qv;
            s[i][3] = s[i][3] * gv + kv * vr3;  a3 += s[i][3] * qv;
        }

        #pragma unroll
        for (int off = 16; off > 0; off >>= 1) {
            a0 += __shfl_xor_sync(0xffffffffu, a0, off);
            a1 += __shfl_xor_sync(0xffffffffu, a1, off);
            a2 += __shfl_xor_sync(0xffffffffu, a2, off);
            a3 += __shfl_xor_sync(0xffffffffu, a3, off);
        }
        if (lane == 0) {
            *(float4*)&attn[((size_t)(b * TSEQ + t)) * VDIM + myv] =
                make_float4(a0, a1, a2, a3);
        }
        __syncthreads();
    }
}

// ---------------------------------------------------------------------------
// Launch
// ---------------------------------------------------------------------------
extern "C" void kernel_launch(void* const* d_in, const int* in_sizes, int n_in,
                              void* d_out, int out_size)
{
    const int*   ids    = (const int*)  d_in[0];
    const float* emb    = (const float*)d_in[1];
    const float* Wq     = (const float*)d_in[2];
    const float* bq     = (const float*)d_in[3];
    const float* Wk     = (const float*)d_in[4];
    const float* bk     = (const float*)d_in[5];
    const float* Wg     = (const float*)d_in[6];
    const float* bg     = (const float*)d_in[7];
    const float* Wv     = (const float*)d_in[8];
    const float* bv     = (const float*)d_in[9];
    const float* Wo     = (const float*)d_in[10];
    const float* bo     = (const float*)d_in[11];
    const float* W_head = (const float*)d_in[12];
    const float* b_head = (const float*)d_in[13];
    float* out = (float*)d_out;

    // Resolve scratch symbol addresses every call (no static caching).
    void* p;
    float *P_H, *P_Q, *P_K, *P_G, *P_V, *P_A;
    cudaGetSymbolAddress(&p, g_h);    P_H = (float*)p;
    cudaGetSymbolAddress(&p, g_q);    P_Q = (float*)p;
    cudaGetSymbolAddress(&p, g_k);    P_K = (float*)p;
    cudaGetSymbolAddress(&p, g_g);    P_G = (float*)p;
    cudaGetSymbolAddress(&p, g_v);    P_V = (float*)p;
    cudaGetSymbolAddress(&p, g_attn); P_A = (float*)p;

    // 1) Embedding gather
    embed_kernel<<<NTOK, 256>>>(ids, emb, P_H);

    // 2) Layers
    for (int l = 0; l < NLAYER; l++) {
        const float* wq = Wq + (size_t)l * HDIM * KDIM;
        const float* wk = Wk + (size_t)l * HDIM * KDIM;
        const float* wg = Wg + (size_t)l * HDIM * KDIM;
        const float* wv = Wv + (size_t)l * HDIM * VDIM;
        const float* wo = Wo + (size_t)l * VDIM * ODIM;

        dim3 gK(KDIM / 128, NTOK / 128);   // (4, 32)
        dim3 gV(VDIM / 128, NTOK / 128);   // (8, 32)

        tf32_gemm_kernel<0><<<gK, 256>>>(P_H, wq, bq + (size_t)l * KDIM, P_Q,
                                         NTOK, KDIM, HDIM);
        tf32_gemm_kernel<1><<<gK, 256>>>(P_H, wk, bk + (size_t)l * KDIM, P_K,
                                         NTOK, KDIM, HDIM);
        tf32_gemm_kernel<1><<<gK, 256>>>(P_H, wg, bg + (size_t)l * KDIM, P_G,
                                         NTOK, KDIM, HDIM);
        tf32_gemm_kernel<0><<<gV, 256>>>(P_H, wv, bv + (size_t)l * VDIM, P_V,
                                         NTOK, VDIM, HDIM);

        scan_kernel<<<128, 256>>>(P_Q, P_K, P_G, P_V, P_A);

        tf32_gemm_kernel<0><<<gV, 256>>>(P_A, wo, bo + (size_t)l * ODIM, P_H,
                                         NTOK, ODIM, VDIM);
    }

    // 3) Head
    dim3 gH(VOCAB / 128, NTOK / 128);      // (250, 32)
    tf32_gemm_kernel<0><<<gH, 256>>>(P_H, W_head, b_head, out,
                                     NTOK, VOCAB, HDIM);
}

// round 11
// speedup vs baseline: 1.4865x; 1.4865x over previous
#include <cuda_runtime.h>
#include <cuda_bf16.h>
#include <math.h>
#include <stddef.h>
#include <stdint.h>

// Problem constants
#define VOCAB 32000
#define HDIM  1024
#define KDIM  512
#define VDIM  1024
#define ODIM  1024
#define NLAYER 2
#define BATCH 4
#define TSEQ  1024
#define NTOK  (BATCH * TSEQ)   // 4096

// ---------------------------------------------------------------------------
// Scratch (device globals — allocation-free per harness rules)
// ---------------------------------------------------------------------------
__device__ float  g_h[NTOK * HDIM];
__device__ float  g_q[NTOK * KDIM];
__device__ float  g_k[NTOK * KDIM];
__device__ float  g_g[NTOK * KDIM];
__device__ float  g_v[NTOK * VDIM];
__device__ float  g_attn[NTOK * VDIM];
__device__ float2 g_asplit[HDIM * NTOK];     // [K][M] (hi,lo) : 32 MB
__device__ float2 g_bsplit[HDIM * VOCAB];    // [K][N] (hi,lo) : 256 MB (max = head)

// ---------------------------------------------------------------------------
// Helpers
// ---------------------------------------------------------------------------
__device__ __forceinline__ unsigned f2tf32(float x) {
    unsigned r;
    asm("cvt.rna.tf32.f32 %0, %1;" : "=r"(r) : "f"(x));
    return r;
}

__device__ __forceinline__ uint32_t smem_u32(const void* p) {
    uint32_t a;
    asm("{ .reg .u64 t; cvta.to.shared.u64 t, %1; cvt.u32.u64 %0, t; }"
        : "=r"(a) : "l"(p));
    return a;
}

__device__ __forceinline__ void cp_async16(uint32_t dst, const void* src) {
    asm volatile("cp.async.cg.shared.global [%0], [%1], 16;"
                 :: "r"(dst), "l"(src));
}
#define CP_COMMIT() asm volatile("cp.async.commit_group;")
#define CP_WAIT(n)  asm volatile("cp.async.wait_group %0;" :: "n"(n))

__device__ __forceinline__ void mma_tf32(float c[4],
                                         unsigned a0, unsigned a1,
                                         unsigned a2, unsigned a3,
                                         unsigned b0, unsigned b1) {
    asm volatile(
        "mma.sync.aligned.m16n8k8.row.col.f32.tf32.tf32.f32 "
        "{%0,%1,%2,%3}, {%4,%5,%6,%7}, {%8,%9}, {%0,%1,%2,%3};"
        : "+f"(c[0]), "+f"(c[1]), "+f"(c[2]), "+f"(c[3])
        : "r"(a0), "r"(a1), "r"(a2), "r"(a3), "r"(b0), "r"(b1));
}

// ---------------------------------------------------------------------------
// Embedding gather
// ---------------------------------------------------------------------------
__global__ void embed_kernel(const int* __restrict__ ids,
                             const float* __restrict__ emb,
                             float* __restrict__ h)
{
    int tok = blockIdx.x;
    int id  = ids[tok];
    const float4* src = (const float4*)(emb + (size_t)id * HDIM);
    float4* dst       = (float4*)(h + (size_t)tok * HDIM);
    dst[threadIdx.x] = src[threadIdx.x];
}

// ---------------------------------------------------------------------------
// Pre-split kernels: fp32 -> (tf32 hi, tf32 lo) interleaved float2.
// split_a also transposes X[M,K] -> Y[K][M] so the GEMM can cp.async rows.
// ---------------------------------------------------------------------------
__global__ void split_a_kernel(const float* __restrict__ X,
                               float2* __restrict__ Y, int M, int K)
{
    __shared__ float t[32][33];
    int k0 = blockIdx.x * 32, m0 = blockIdx.y * 32;
    int tx = threadIdx.x, ty = threadIdx.y;   // block (32, 8)
    #pragma unroll
    for (int j = 0; j < 4; j++)
        t[ty + 8 * j][tx] = X[(size_t)(m0 + ty + 8 * j) * K + k0 + tx];
    __syncthreads();
    #pragma unroll
    for (int j = 0; j < 4; j++) {
        float v = t[tx][ty + 8 * j];
        unsigned hi = f2tf32(v);
        unsigned lo = f2tf32(v - __uint_as_float(hi));
        Y[(size_t)(k0 + ty + 8 * j) * M + m0 + tx] =
            make_float2(__uint_as_float(hi), __uint_as_float(lo));
    }
}

__global__ void split_b_kernel(const float* __restrict__ W,
                               float2* __restrict__ Y, int n)
{
    int i = blockIdx.x * 256 + threadIdx.x;
    if (i < n) {
        float v = W[i];
        unsigned hi = f2tf32(v);
        unsigned lo = f2tf32(v - __uint_as_float(hi));
        Y[i] = make_float2(__uint_as_float(hi), __uint_as_float(lo));
    }
}

// ---------------------------------------------------------------------------
// TF32 mma.sync GEMM, 3xTF32 split, pre-split inputs:
//   C[M,N] = A @ B + bias  (opt sigmoid)
// Ahl: [K][M] float2 (hi,lo).  Bhl: [K][N] float2.
// CTA tile 128x128, k-slab 16, cp.async double buffer, 256 thr, 8 warps
// (warp tile 64x32 = 4x4 m16n8k8). Smem stride 132 float2 -> conflict-free
// fragment LDS.64 (bank = 8*tig + 2*grp, distinct per half-warp).
// M,N,K all multiples of tile sizes here; no bounds checks. K mult of 16.
// ---------------------------------------------------------------------------
#define SROW   132                  // float2 per smem k-row (128 + pad)
#define STILE  (16 * SROW)          // float2 per tile buffer (2112)
#define SBUF   (2 * STILE)          // A + B per stage (4224 float2)
#define GEMM_SMEM (2 * SBUF * 8)    // bytes = 67584

template<int ACT>
__global__ __launch_bounds__(256)
void tc_gemm(const float2* __restrict__ Ahl,
             const float2* __restrict__ Bhl,
             const float*  __restrict__ bias,
             float* __restrict__ C,
             int M, int N, int K)
{
    extern __shared__ float2 sm[];
    const int tid  = threadIdx.x;
    const int by   = blockIdx.x;        // M tile
    const int bx   = blockIdx.y;        // N tile
    const int warp = tid >> 5;
    const int lane = tid & 31;
    const int grp  = lane >> 2;         // 0..7
    const int tig  = lane & 3;          // 0..3
    const int wm   = (warp >> 2) * 64;
    const int wn   = (warp & 3) * 32;
    const int m0g  = by * 128;
    const int n0g  = bx * 128;

    const uint32_t sb = smem_u32(sm);

    float acc[4][4][4];
    #pragma unroll
    for (int i = 0; i < 4; i++)
        #pragma unroll
        for (int j = 0; j < 4; j++)
            #pragma unroll
            for (int r = 0; r < 4; r++) acc[i][j][r] = 0.0f;

    // ---- async copy of one k-slab (16 k-rows of A and B) into buffer `buf`
    auto issue = [&](int k0, int buf) {
        uint32_t ab = sb + (uint32_t)buf * (SBUF * 8);
        uint32_t bb = ab + STILE * 8;
        #pragma unroll
        for (int i = 0; i < 4; i++) {
            int c   = tid + i * 256;       // 0..1023
            int r   = c >> 6;              // k-row 0..15
            int col = c & 63;              // 16B chunk
            cp_async16(ab + (uint32_t)r * (SROW * 8) + col * 16,
                       (const char*)(Ahl + (size_t)(k0 + r) * M + m0g) + col * 16);
            cp_async16(bb + (uint32_t)r * (SROW * 8) + col * 16,
                       (const char*)(Bhl + (size_t)(k0 + r) * N + n0g) + col * 16);
        }
    };

    issue(0, 0);
    CP_COMMIT();

    const int nIter = K >> 4;
    for (int it = 0; it < nIter; it++) {
        const int buf = it & 1;
        if (it + 1 < nIter) {
            issue((it + 1) << 4, buf ^ 1);
            CP_COMMIT();
            CP_WAIT(1);
        } else {
            CP_WAIT(0);
        }
        __syncthreads();

        const float2* As = sm + buf * SBUF;
        const float2* Bs = As + STILE;

        #pragma unroll
        for (int ks = 0; ks < 2; ks++) {
            const int kb = ks * 8;
            float2 af[4][4], bf[4][2];
            #pragma unroll
            for (int mt = 0; mt < 4; mt++) {
                int m0 = wm + mt * 16 + grp;
                af[mt][0] = As[(kb + tig) * SROW + m0];
                af[mt][1] = As[(kb + tig) * SROW + m0 + 8];
                af[mt][2] = As[(kb + tig + 4) * SROW + m0];
                af[mt][3] = As[(kb + tig + 4) * SROW + m0 + 8];
            }
            #pragma unroll
            for (int nt = 0; nt < 4; nt++) {
                int n0 = wn + nt * 8 + grp;
                bf[nt][0] = Bs[(kb + tig) * SROW + n0];
                bf[nt][1] = Bs[(kb + tig + 4) * SROW + n0];
            }
            #pragma unroll
            for (int mt = 0; mt < 4; mt++)
                #pragma unroll
                for (int nt = 0; nt < 4; nt++) {
                    // hi*hi
                    mma_tf32(acc[mt][nt],
                             __float_as_uint(af[mt][0].x), __float_as_uint(af[mt][1].x),
                             __float_as_uint(af[mt][2].x), __float_as_uint(af[mt][3].x),
                             __float_as_uint(bf[nt][0].x), __float_as_uint(bf[nt][1].x));
                    // lo*hi
                    mma_tf32(acc[mt][nt],
                             __float_as_uint(af[mt][0].y), __float_as_uint(af[mt][1].y),
                             __float_as_uint(af[mt][2].y), __float_as_uint(af[mt][3].y),
                             __float_as_uint(bf[nt][0].x), __float_as_uint(bf[nt][1].x));
                    // hi*lo
                    mma_tf32(acc[mt][nt],
                             __float_as_uint(af[mt][0].x), __float_as_uint(af[mt][1].x),
                             __float_as_uint(af[mt][2].x), __float_as_uint(af[mt][3].x),
                             __float_as_uint(bf[nt][0].y), __float_as_uint(bf[nt][1].y));
                }
        }
        __syncthreads();
    }

    // ---- epilogue (fragment->C mapping proven in R9)
    #pragma unroll
    for (int nt = 0; nt < 4; nt++) {
        int col = n0g + wn + nt * 8 + tig * 2;
        float2 bs = *(const float2*)(bias + col);
        #pragma unroll
        for (int mt = 0; mt < 4; mt++) {
            int row0 = m0g + wm + mt * 16 + grp;
            float v0 = acc[mt][nt][0] + bs.x;
            float v1 = acc[mt][nt][1] + bs.y;
            float v2 = acc[mt][nt][2] + bs.x;
            float v3 = acc[mt][nt][3] + bs.y;
            if (ACT == 1) {
                v0 = 1.0f / (1.0f + __expf(-v0));
                v1 = 1.0f / (1.0f + __expf(-v1));
                v2 = 1.0f / (1.0f + __expf(-v2));
                v3 = 1.0f / (1.0f + __expf(-v3));
            }
            *(float2*)(C + (size_t)row0 * N + col)       = make_float2(v0, v1);
            *(float2*)(C + (size_t)(row0 + 8) * N + col) = make_float2(v2, v3);
        }
    }
}

// ---------------------------------------------------------------------------
// Gated linear-attention scan (register-resident state; unchanged)
// ---------------------------------------------------------------------------
__global__ __launch_bounds__(256)
void scan_kernel(const float* __restrict__ q,
                 const float* __restrict__ kk,
                 const float* __restrict__ gg,
                 const float* __restrict__ vv,
                 float* __restrict__ attn)
{
    const int b    = blockIdx.x >> 5;
    const int vblk = blockIdx.x & 31;
    const int v0   = vblk * 32;
    const int warp = threadIdx.x >> 5;
    const int lane = threadIdx.x & 31;
    const int myv  = v0 + warp * 4;

    __shared__ float sq[KDIM];
    __shared__ float sk[KDIM];
    __shared__ float sg[KDIM];
    __shared__ float sv[32];

    float s[16][4];
    #pragma unroll
    for (int i = 0; i < 16; i++)
        #pragma unroll
        for (int j = 0; j < 4; j++) s[i][j] = 0.0f;

    const float* qb = q  + (size_t)b * TSEQ * KDIM;
    const float* kb = kk + (size_t)b * TSEQ * KDIM;
    const float* gb = gg + (size_t)b * TSEQ * KDIM;
    const float* vb = vv + (size_t)b * TSEQ * VDIM;

    for (int t = 0; t < TSEQ; t++) {
        const float* qt = qb + (size_t)t * KDIM;
        const float* kt = kb + (size_t)t * KDIM;
        const float* gt = gb + (size_t)t * KDIM;
        #pragma unroll
        for (int i = threadIdx.x; i < KDIM; i += 256) {
            sq[i] = qt[i];
            sk[i] = kt[i];
            sg[i] = gt[i];
        }
        if (threadIdx.x < 32)
            sv[threadIdx.x] = vb[(size_t)t * VDIM + v0 + threadIdx.x];
        __syncthreads();

        float vr0 = sv[warp * 4 + 0];
        float vr1 = sv[warp * 4 + 1];
        float vr2 = sv[warp * 4 + 2];
        float vr3 = sv[warp * 4 + 3];

        float a0 = 0.f, a1 = 0.f, a2 = 0.f, a3 = 0.f;
        #pragma unroll
        for (int i = 0; i < 16; i++) {
            int kidx = i * 32 + lane;
            float qv = sq[kidx];
            float kv = sk[kidx];
            float gv = sg[kidx];
            s[i][0] = s[i][0] * gv + kv * vr0;  a0 += s[i][0] * qv;
            s[i][1] = s[i][1] * gv + kv * vr1;  a1 += s[i][1] * qv;
            s[i][2] = s[i][2] * gv + kv * vr2;  a2 += s[i][2] * qv;
            s[i][3] = s[i][3] * gv + kv * vr3;  a3 += s[i][3] * qv;
        }

        #pragma unroll
        for (int off = 16; off > 0; off >>= 1) {
            a0 += __shfl_xor_sync(0xffffffffu, a0, off);
            a1 += __shfl_xor_sync(0xffffffffu, a1, off);
            a2 += __shfl_xor_sync(0xffffffffu, a2, off);
            a3 += __shfl_xor_sync(0xffffffffu, a3, off);
        }
        if (lane == 0) {
            *(float4*)&attn[((size_t)(b * TSEQ + t)) * VDIM + myv] =
                make_float4(a0, a1, a2, a3);
        }
        __syncthreads();
    }
}

// ---------------------------------------------------------------------------
// Launch
// ---------------------------------------------------------------------------
extern "C" void kernel_launch(void* const* d_in, const int* in_sizes, int n_in,
                              void* d_out, int out_size)
{
    const int*   ids    = (const int*)  d_in[0];
    const float* emb    = (const float*)d_in[1];
    const float* Wq     = (const float*)d_in[2];
    const float* bq     = (const float*)d_in[3];
    const float* Wk     = (const float*)d_in[4];
    const float* bk     = (const float*)d_in[5];
    const float* Wg     = (const float*)d_in[6];
    const float* bg     = (const float*)d_in[7];
    const float* Wv     = (const float*)d_in[8];
    const float* bv     = (const float*)d_in[9];
    const float* Wo     = (const float*)d_in[10];
    const float* bo     = (const float*)d_in[11];
    const float* W_head = (const float*)d_in[12];
    const float* b_head = (const float*)d_in[13];
    float* out = (float*)d_out;

    void* p;
    float  *P_H, *P_Q, *P_K, *P_G, *P_V, *P_A;
    float2 *P_AS, *P_BS;
    cudaGetSymbolAddress(&p, g_h);      P_H  = (float*)p;
    cudaGetSymbolAddress(&p, g_q);      P_Q  = (float*)p;
    cudaGetSymbolAddress(&p, g_k);      P_K  = (float*)p;
    cudaGetSymbolAddress(&p, g_g);      P_G  = (float*)p;
    cudaGetSymbolAddress(&p, g_v);      P_V  = (float*)p;
    cudaGetSymbolAddress(&p, g_attn);   P_A  = (float*)p;
    cudaGetSymbolAddress(&p, g_asplit); P_AS = (float2*)p;
    cudaGetSymbolAddress(&p, g_bsplit); P_BS = (float2*)p;

    cudaFuncSetAttribute(tc_gemm<0>,
                         cudaFuncAttributeMaxDynamicSharedMemorySize, GEMM_SMEM);
    cudaFuncSetAttribute(tc_gemm<1>,
                         cudaFuncAttributeMaxDynamicSharedMemorySize, GEMM_SMEM);

    // 1) Embedding gather
    embed_kernel<<<NTOK, 256>>>(ids, emb, P_H);

    dim3 tb(32, 8);
    dim3 gaT(HDIM / 32, NTOK / 32);            // split h/attn (K=1024, M=4096)
    dim3 gK(NTOK / 128, KDIM / 128);           // (32, 4)
    dim3 gV(NTOK / 128, VDIM / 128);           // (32, 8)

    // 2) Layers
    for (int l = 0; l < NLAYER; l++) {
        const float* wq = Wq + (size_t)l * HDIM * KDIM;
        const float* wk = Wk + (size_t)l * HDIM * KDIM;
        const float* wg = Wg + (size_t)l * HDIM * KDIM;
        const float* wv = Wv + (size_t)l * HDIM * VDIM;
        const float* wo = Wo + (size_t)l * VDIM * ODIM;

        split_a_kernel<<<gaT, tb>>>(P_H, P_AS, NTOK, HDIM);

        split_b_kernel<<<(HDIM * KDIM) / 256, 256>>>(wq, P_BS, HDIM * KDIM);
        tc_gemm<0><<<gK, 256, GEMM_SMEM>>>(P_AS, P_BS, bq + (size_t)l * KDIM,
                                           P_Q, NTOK, KDIM, HDIM);
        split_b_kernel<<<(HDIM * KDIM) / 256, 256>>>(wk, P_BS, HDIM * KDIM);
        tc_gemm<1><<<gK, 256, GEMM_SMEM>>>(P_AS, P_BS, bk + (size_t)l * KDIM,
                                           P_K, NTOK, KDIM, HDIM);
        split_b_kernel<<<(HDIM * KDIM) / 256, 256>>>(wg, P_BS, HDIM * KDIM);
        tc_gemm<1><<<gK, 256, GEMM_SMEM>>>(P_AS, P_BS, bg + (size_t)l * KDIM,
                                           P_G, NTOK, KDIM, HDIM);
        split_b_kernel<<<(HDIM * VDIM) / 256, 256>>>(wv, P_BS, HDIM * VDIM);
        tc_gemm<0><<<gV, 256, GEMM_SMEM>>>(P_AS, P_BS, bv + (size_t)l * VDIM,
                                           P_V, NTOK, VDIM, HDIM);

        scan_kernel<<<128, 256>>>(P_Q, P_K, P_G, P_V, P_A);

        split_a_kernel<<<gaT, tb>>>(P_A, P_AS, NTOK, VDIM);
        split_b_kernel<<<(VDIM * ODIM) / 256, 256>>>(wo, P_BS, VDIM * ODIM);
        tc_gemm<0><<<gV, 256, GEMM_SMEM>>>(P_AS, P_BS, bo + (size_t)l * ODIM,
                                           P_H, NTOK, ODIM, VDIM);
    }

    // 3) Head
    split_a_kernel<<<gaT, tb>>>(P_H, P_AS, NTOK, HDIM);
    split_b_kernel<<<(HDIM * VOCAB) / 256, 256>>>(W_head, P_BS, HDIM * VOCAB);
    dim3 gH(NTOK / 128, VOCAB / 128);          // (32, 250)
    tc_gemm<0><<<gH, 256, GEMM_SMEM>>>(P_AS, P_BS, b_head, out,
                                       NTOK, VOCAB, HDIM);
}

// round 16
// speedup vs baseline: 2.0725x; 1.3943x over previous
#include <cuda_runtime.h>
#include <cuda_fp16.h>
#include <math.h>
#include <stddef.h>
#include <stdint.h>

// Problem constants
#define VOCAB 32000
#define HDIM  1024
#define KDIM  512
#define VDIM  1024
#define ODIM  1024
#define NLAYER 2
#define BATCH 4
#define TSEQ  1024
#define NTOK  (BATCH * TSEQ)   // 4096

#define LO_SCALE 2048.0f
#define LO_INV   (1.0f / 2048.0f)

// ---------------------------------------------------------------------------
// Scratch (device globals — allocation-free per harness rules)
// Split buffers: float2 per k-pair:
//   .x = half2(hi_k, hi_{k+1}),  .y = half2(2048*lo_k, 2048*lo_{k+1}).
// Layout [k/2][M] (A, transposed) and [k/2][N] (B).
// ---------------------------------------------------------------------------
__device__ float  g_h[NTOK * HDIM];
__device__ float  g_q[NTOK * KDIM];
__device__ float  g_k[NTOK * KDIM];
__device__ float  g_g[NTOK * KDIM];
__device__ float  g_v[NTOK * VDIM];
__device__ float  g_attn[NTOK * VDIM];
__device__ float2 g_asplit[(HDIM / 2) * NTOK];    // 16 MB
__device__ float2 g_bsplit[(HDIM / 2) * VOCAB];   // 131 MB (max = head)

// ---------------------------------------------------------------------------
// Helpers
// ---------------------------------------------------------------------------
__device__ __forceinline__ uint32_t smem_u32(const void* p) {
    uint32_t a;
    asm("{ .reg .u64 t; cvta.to.shared.u64 t, %1; cvt.u32.u64 %0, t; }"
        : "=r"(a) : "l"(p));
    return a;
}

__device__ __forceinline__ void cp_async16(uint32_t dst, const void* src) {
    asm volatile("cp.async.cg.shared.global [%0], [%1], 16;"
                 :: "r"(dst), "l"(src));
}
#define CP_COMMIT() asm volatile("cp.async.commit_group;")
#define CP_WAIT(n)  asm volatile("cp.async.wait_group %0;" :: "n"(n))

// fp16 split of two consecutive k-values; lo scaled by 2048 so it stays in
// the fp16 NORMAL range (unscaled lo of 0.02-scale data is subnormal and
// gets flushed/quantized to nothing — the R13 failure mode).
__device__ __forceinline__ float2 split16(float v0, float v1) {
    __half h0 = __float2half_rn(v0), h1 = __float2half_rn(v1);
    __half l0 = __float2half_rn((v0 - __half2float(h0)) * LO_SCALE);
    __half l1 = __float2half_rn((v1 - __half2float(h1)) * LO_SCALE);
    __half2 hp = __halves2half2(h0, h1);
    __half2 lp = __halves2half2(l0, l1);
    float2 o;
    o.x = __uint_as_float(*reinterpret_cast<unsigned*>(&hp));
    o.y = __uint_as_float(*reinterpret_cast<unsigned*>(&lp));
    return o;
}

__device__ __forceinline__ void mma_f16(float c[4],
                                        unsigned a0, unsigned a1,
                                        unsigned a2, unsigned a3,
                                        unsigned b0, unsigned b1) {
    asm volatile(
        "mma.sync.aligned.m16n8k16.row.col.f32.f16.f16.f32 "
        "{%0,%1,%2,%3}, {%4,%5,%6,%7}, {%8,%9}, {%0,%1,%2,%3};"
        : "+f"(c[0]), "+f"(c[1]), "+f"(c[2]), "+f"(c[3])
        : "r"(a0), "r"(a1), "r"(a2), "r"(a3), "r"(b0), "r"(b1));
}

// ---------------------------------------------------------------------------
// Embedding gather
// ---------------------------------------------------------------------------
__global__ void embed_kernel(const int* __restrict__ ids,
                             const float* __restrict__ emb,
                             float* __restrict__ h)
{
    int tok = blockIdx.x;
    int id  = ids[tok];
    const float4* src = (const float4*)(emb + (size_t)id * HDIM);
    float4* dst       = (float4*)(h + (size_t)tok * HDIM);
    dst[threadIdx.x] = src[threadIdx.x];
}

// ---------------------------------------------------------------------------
// Pre-split: activations X[M,K] -> Y[k/2][M] (transpose + fp16 hi/lo pairs)
// t[m_local][k_local]; pairing runs over k (second index) for fixed m = tx.
// ---------------------------------------------------------------------------
__global__ void split_a_kernel(const float* __restrict__ X,
                               float2* __restrict__ Y, int M, int K)
{
    __shared__ float t[32][33];
    int k0 = blockIdx.x * 32, m0 = blockIdx.y * 32;
    int tx = threadIdx.x, ty = threadIdx.y;   // block (32, 8)
    #pragma unroll
    for (int j = 0; j < 4; j++)
        t[ty + 8 * j][tx] = X[(size_t)(m0 + ty + 8 * j) * K + k0 + tx];
    __syncthreads();
    #pragma unroll
    for (int j = 0; j < 2; j++) {
        int pi = ty + 8 * j;                  // k-pair index 0..15
        float v0 = t[tx][2 * pi];             // m = m0+tx, k = k0+2pi
        float v1 = t[tx][2 * pi + 1];         // m = m0+tx, k = k0+2pi+1
        Y[(size_t)(k0 / 2 + pi) * M + m0 + tx] = split16(v0, v1);
    }
}

// Weights W[K,N] -> Y[k/2][N] (fp16 hi/lo pairs; no transpose needed)
__global__ void split_b_kernel(const float* __restrict__ W,
                               float2* __restrict__ Y, int KH, int N)
{
    int i = blockIdx.x * 256 + threadIdx.x;
    if (i < KH * N) {
        int kp = i / N, n = i - kp * N;
        float v0 = W[(size_t)(2 * kp) * N + n];
        float v1 = W[(size_t)(2 * kp + 1) * N + n];
        Y[i] = split16(v0, v1);
    }
}

// ---------------------------------------------------------------------------
// FP16 mma.sync GEMM, 3-term split with scaled-lo dual accumulators:
//   C = (acc_hi + acc_lo/2048) + bias   (opt sigmoid)
// acc_hi  += hi_a*hi_b
// acc_lo  += lo'_a*hi_b + hi_a*lo'_b          (lo' = 2048*lo)
// CTA tile 128x128; k-slab = 32 k (16 pair-rows); cp.async double buffer;
// 256 thr, 8 warps, warp tile 64x32 = 4x4 m16n8k16.
// SROW=132 float2 smem rows -> conflict-free LDS.64 fragment loads.
// ---------------------------------------------------------------------------
#define SROW   132
#define STILE  (16 * SROW)
#define SBUF   (2 * STILE)
#define GEMM_SMEM (2 * SBUF * 8)    // 67584 bytes

template<int ACT>
__global__ __launch_bounds__(256)
void tc_gemm(const float2* __restrict__ Ahl,
             const float2* __restrict__ Bhl,
             const float*  __restrict__ bias,
             float* __restrict__ C,
             int M, int N, int K)
{
    extern __shared__ float2 sm[];
    const int tid  = threadIdx.x;
    const int by   = blockIdx.x;        // M tile
    const int bx   = blockIdx.y;        // N tile
    const int warp = tid >> 5;
    const int lane = tid & 31;
    const int grp  = lane >> 2;
    const int tig  = lane & 3;
    const int wm   = (warp >> 2) * 64;
    const int wn   = (warp & 3) * 32;
    const int m0g  = by * 128;
    const int n0g  = bx * 128;

    const uint32_t sb = smem_u32(sm);

    float accH[4][4][4], accL[4][4][4];
    #pragma unroll
    for (int i = 0; i < 4; i++)
        #pragma unroll
        for (int j = 0; j < 4; j++)
            #pragma unroll
            for (int r = 0; r < 4; r++) { accH[i][j][r] = 0.0f; accL[i][j][r] = 0.0f; }

    auto issue = [&](int kp0, int buf) {
        uint32_t ab = sb + (uint32_t)buf * (SBUF * 8);
        uint32_t bb = ab + STILE * 8;
        #pragma unroll
        for (int i = 0; i < 4; i++) {
            int c   = tid + i * 256;
            int r   = c >> 6;
            int col = c & 63;
            cp_async16(ab + (uint32_t)r * (SROW * 8) + col * 16,
                       (const char*)(Ahl + (size_t)(kp0 + r) * M + m0g) + col * 16);
            cp_async16(bb + (uint32_t)r * (SROW * 8) + col * 16,
                       (const char*)(Bhl + (size_t)(kp0 + r) * N + n0g) + col * 16);
        }
    };

    issue(0, 0);
    CP_COMMIT();

    const int nIter = K >> 5;              // 32-k slabs
    for (int it = 0; it < nIter; it++) {
        const int buf = it & 1;
        if (it + 1 < nIter) {
            issue((it + 1) << 4, buf ^ 1);
            CP_COMMIT();
            CP_WAIT(1);
        } else {
            CP_WAIT(0);
        }
        __syncthreads();

        const float2* As = sm + buf * SBUF;
        const float2* Bs = As + STILE;

        #pragma unroll
        for (int ks = 0; ks < 2; ks++) {   // each ks = 8 pair-rows = k16
            const int kb = ks * 8;
            float2 af[4][4], bf[4][2];
            #pragma unroll
            for (int mt = 0; mt < 4; mt++) {
                int m0 = wm + mt * 16 + grp;
                af[mt][0] = As[(kb + tig) * SROW + m0];
                af[mt][1] = As[(kb + tig) * SROW + m0 + 8];
                af[mt][2] = As[(kb + tig + 4) * SROW + m0];
                af[mt][3] = As[(kb + tig + 4) * SROW + m0 + 8];
            }
            #pragma unroll
            for (int nt = 0; nt < 4; nt++) {
                int n0 = wn + nt * 8 + grp;
                bf[nt][0] = Bs[(kb + tig) * SROW + n0];
                bf[nt][1] = Bs[(kb + tig + 4) * SROW + n0];
            }
            #pragma unroll
            for (int mt = 0; mt < 4; mt++)
                #pragma unroll
                for (int nt = 0; nt < 4; nt++) {
                    // hi*hi -> accH
                    mma_f16(accH[mt][nt],
                            __float_as_uint(af[mt][0].x), __float_as_uint(af[mt][1].x),
                            __float_as_uint(af[mt][2].x), __float_as_uint(af[mt][3].x),
                            __float_as_uint(bf[nt][0].x), __float_as_uint(bf[nt][1].x));
                    // lo'*hi -> accL
                    mma_f16(accL[mt][nt],
                            __float_as_uint(af[mt][0].y), __float_as_uint(af[mt][1].y),
                            __float_as_uint(af[mt][2].y), __float_as_uint(af[mt][3].y),
                            __float_as_uint(bf[nt][0].x), __float_as_uint(bf[nt][1].x));
                    // hi*lo' -> accL
                    mma_f16(accL[mt][nt],
                            __float_as_uint(af[mt][0].x), __float_as_uint(af[mt][1].x),
                            __float_as_uint(af[mt][2].x), __float_as_uint(af[mt][3].x),
                            __float_as_uint(bf[nt][0].y), __float_as_uint(bf[nt][1].y));
                }
        }
        __syncthreads();
    }

    // epilogue: C = accH + accL/2048 + bias
    #pragma unroll
    for (int nt = 0; nt < 4; nt++) {
        int col = n0g + wn + nt * 8 + tig * 2;
        float2 bs = *(const float2*)(bias + col);
        #pragma unroll
        for (int mt = 0; mt < 4; mt++) {
            int row0 = m0g + wm + mt * 16 + grp;
            float v0 = fmaf(accL[mt][nt][0], LO_INV, accH[mt][nt][0]) + bs.x;
            float v1 = fmaf(accL[mt][nt][1], LO_INV, accH[mt][nt][1]) + bs.y;
            float v2 = fmaf(accL[mt][nt][2], LO_INV, accH[mt][nt][2]) + bs.x;
            float v3 = fmaf(accL[mt][nt][3], LO_INV, accH[mt][nt][3]) + bs.y;
            if (ACT == 1) {
                v0 = 1.0f / (1.0f + __expf(-v0));
                v1 = 1.0f / (1.0f + __expf(-v1));
                v2 = 1.0f / (1.0f + __expf(-v2));
                v3 = 1.0f / (1.0f + __expf(-v3));
            }
            *(float2*)(C + (size_t)row0 * N + col)       = make_float2(v0, v1);
            *(float2*)(C + (size_t)(row0 + 8) * N + col) = make_float2(v2, v3);
        }
    }
}

// ---------------------------------------------------------------------------
// Gated linear-attention scan (register-resident state; unchanged)
// ---------------------------------------------------------------------------
__global__ __launch_bounds__(256)
void scan_kernel(const float* __restrict__ q,
                 const float* __restrict__ kk,
                 const float* __restrict__ gg,
                 const float* __restrict__ vv,
                 float* __restrict__ attn)
{
    const int b    = blockIdx.x >> 5;
    const int vblk = blockIdx.x & 31;
    const int v0   = vblk * 32;
    const int warp = threadIdx.x >> 5;
    const int lane = threadIdx.x & 31;
    const int myv  = v0 + warp * 4;

    __shared__ float sq[KDIM];
    __shared__ float sk[KDIM];
    __shared__ float sg[KDIM];
    __shared__ float sv[32];

    float s[16][4];
    #pragma unroll
    for (int i = 0; i < 16; i++)
        #pragma unroll
        for (int j = 0; j < 4; j++) s[i][j] = 0.0f;

    const float* qb = q  + (size_t)b * TSEQ * KDIM;
    const float* kb = kk + (size_t)b * TSEQ * KDIM;
    const float* gb = gg + (size_t)b * TSEQ * KDIM;
    const float* vb = vv + (size_t)b * TSEQ * VDIM;

    for (int t = 0; t < TSEQ; t++) {
        const float* qt = qb + (size_t)t * KDIM;
        const float* kt = kb + (size_t)t * KDIM;
        const float* gt = gb + (size_t)t * KDIM;
        #pragma unroll
        for (int i = threadIdx.x; i < KDIM; i += 256) {
            sq[i] = qt[i];
            sk[i] = kt[i];
            sg[i] = gt[i];
        }
        if (threadIdx.x < 32)
            sv[threadIdx.x] = vb[(size_t)t * VDIM + v0 + threadIdx.x];
        __syncthreads();

        float vr0 = sv[warp * 4 + 0];
        float vr1 = sv[warp * 4 + 1];
        float vr2 = sv[warp * 4 + 2];
        float vr3 = sv[warp * 4 + 3];

        float a0 = 0.f, a1 = 0.f, a2 = 0.f, a3 = 0.f;
        #pragma unroll
        for (int i = 0; i < 16; i++) {
            int kidx = i * 32 + lane;
            float qv = sq[kidx];
            float kv = sk[kidx];
            float gv = sg[kidx];
            s[i][0] = s[i][0] * gv + kv * vr0;  a0 += s[i][0] * qv;
            s[i][1] = s[i][1] * gv + kv * vr1;  a1 += s[i][1] * qv;
            s[i][2] = s[i][2] * gv + kv * vr2;  a2 += s[i][2] * qv;
            s[i][3] = s[i][3] * gv + kv * vr3;  a3 += s[i][3] * qv;
        }

        #pragma unroll
        for (int off = 16; off > 0; off >>= 1) {
            a0 += __shfl_xor_sync(0xffffffffu, a0, off);
            a1 += __shfl_xor_sync(0xffffffffu, a1, off);
            a2 += __shfl_xor_sync(0xffffffffu, a2, off);
            a3 += __shfl_xor_sync(0xffffffffu, a3, off);
        }
        if (lane == 0) {
            *(float4*)&attn[((size_t)(b * TSEQ + t)) * VDIM + myv] =
                make_float4(a0, a1, a2, a3);
        }
        __syncthreads();
    }
}

// ---------------------------------------------------------------------------
// Launch
// ---------------------------------------------------------------------------
extern "C" void kernel_launch(void* const* d_in, const int* in_sizes, int n_in,
                              void* d_out, int out_size)
{
    const int*   ids    = (const int*)  d_in[0];
    const float* emb    = (const float*)d_in[1];
    const float* Wq     = (const float*)d_in[2];
    const float* bq     = (const float*)d_in[3];
    const float* Wk     = (const float*)d_in[4];
    const float* bk     = (const float*)d_in[5];
    const float* Wg     = (const float*)d_in[6];
    const float* bg     = (const float*)d_in[7];
    const float* Wv     = (const float*)d_in[8];
    const float* bv     = (const float*)d_in[9];
    const float* Wo     = (const float*)d_in[10];
    const float* bo     = (const float*)d_in[11];
    const float* W_head = (const float*)d_in[12];
    const float* b_head = (const float*)d_in[13];
    float* out = (float*)d_out;

    void* p;
    float  *P_H, *P_Q, *P_K, *P_G, *P_V, *P_A;
    float2 *P_AS, *P_BS;
    cudaGetSymbolAddress(&p, g_h);      P_H  = (float*)p;
    cudaGetSymbolAddress(&p, g_q);      P_Q  = (float*)p;
    cudaGetSymbolAddress(&p, g_k);      P_K  = (float*)p;
    cudaGetSymbolAddress(&p, g_g);      P_G  = (float*)p;
    cudaGetSymbolAddress(&p, g_v);      P_V  = (float*)p;
    cudaGetSymbolAddress(&p, g_attn);   P_A  = (float*)p;
    cudaGetSymbolAddress(&p, g_asplit); P_AS = (float2*)p;
    cudaGetSymbolAddress(&p, g_bsplit); P_BS = (float2*)p;

    cudaFuncSetAttribute(tc_gemm<0>,
                         cudaFuncAttributeMaxDynamicSharedMemorySize, GEMM_SMEM);
    cudaFuncSetAttribute(tc_gemm<1>,
                         cudaFuncAttributeMaxDynamicSharedMemorySize, GEMM_SMEM);

    // 1) Embedding gather
    embed_kernel<<<NTOK, 256>>>(ids, emb, P_H);

    dim3 tb(32, 8);
    dim3 gaT(HDIM / 32, NTOK / 32);
    dim3 gK(NTOK / 128, KDIM / 128);           // (32, 4)
    dim3 gV(NTOK / 128, VDIM / 128);           // (32, 8)

    const int nbK = ((HDIM / 2) * KDIM + 255) / 256;
    const int nbV = ((HDIM / 2) * VDIM + 255) / 256;
    const int nbO = ((VDIM / 2) * ODIM + 255) / 256;

    // 2) Layers
    for (int l = 0; l < NLAYER; l++) {
        const float* wq = Wq + (size_t)l * HDIM * KDIM;
        const float* wk = Wk + (size_t)l * HDIM * KDIM;
        const float* wg = Wg + (size_t)l * HDIM * KDIM;
        const float* wv = Wv + (size_t)l * HDIM * VDIM;
        const float* wo = Wo + (size_t)l * VDIM * ODIM;

        split_a_kernel<<<gaT, tb>>>(P_H, P_AS, NTOK, HDIM);

        split_b_kernel<<<nbK, 256>>>(wq, P_BS, HDIM / 2, KDIM);
        tc_gemm<0><<<gK, 256, GEMM_SMEM>>>(P_AS, P_BS, bq + (size_t)l * KDIM,
                                           P_Q, NTOK, KDIM, HDIM);
        split_b_kernel<<<nbK, 256>>>(wk, P_BS, HDIM / 2, KDIM);
        tc_gemm<1><<<gK, 256, GEMM_SMEM>>>(P_AS, P_BS, bk + (size_t)l * KDIM,
                                           P_K, NTOK, KDIM, HDIM);
        split_b_kernel<<<nbK, 256>>>(wg, P_BS, HDIM / 2, KDIM);
        tc_gemm<1><<<gK, 256, GEMM_SMEM>>>(P_AS, P_BS, bg + (size_t)l * KDIM,
                                           P_G, NTOK, KDIM, HDIM);
        split_b_kernel<<<nbV, 256>>>(wv, P_BS, HDIM / 2, VDIM);
        tc_gemm<0><<<gV, 256, GEMM_SMEM>>>(P_AS, P_BS, bv + (size_t)l * VDIM,
                                           P_V, NTOK, VDIM, HDIM);

        scan_kernel<<<128, 256>>>(P_Q, P_K, P_G, P_V, P_A);

        split_a_kernel<<<gaT, tb>>>(P_A, P_AS, NTOK, VDIM);
        split_b_kernel<<<nbO, 256>>>(wo, P_BS, VDIM / 2, ODIM);
        tc_gemm<0><<<gV, 256, GEMM_SMEM>>>(P_AS, P_BS, bo + (size_t)l * ODIM,
                                           P_H, NTOK, ODIM, VDIM);
    }

    // 3) Head
    split_a_kernel<<<gaT, tb>>>(P_H, P_AS, NTOK, HDIM);
    const int nbH = ((HDIM / 2) * VOCAB + 255) / 256;
    split_b_kernel<<<nbH, 256>>>(W_head, P_BS, HDIM / 2, VOCAB);
    dim3 gH(NTOK / 128, VOCAB / 128);          // (32, 250)
    tc_gemm<0><<<gH, 256, GEMM_SMEM>>>(P_AS, P_BS, b_head, out,
                                       NTOK, VOCAB, HDIM);
}

// round 17
// speedup vs baseline: 2.1851x; 1.0543x over previous
#include <cuda_runtime.h>
#include <cuda_fp16.h>
#include <math.h>
#include <stddef.h>
#include <stdint.h>

// Problem constants
#define VOCAB 32000
#define HDIM  1024
#define KDIM  512
#define VDIM  1024
#define ODIM  1024
#define NLAYER 2
#define BATCH 4
#define TSEQ  1024
#define NTOK  (BATCH * TSEQ)   // 4096

#define LO_SCALE 2048.0f
#define LO_INV   (1.0f / 2048.0f)

// ---------------------------------------------------------------------------
// Scratch (device globals — allocation-free per harness rules)
// Split buffers: float2 per k-pair:
//   .x = half2(hi_k, hi_{k+1}),  .y = half2(2048*lo_k, 2048*lo_{k+1}).
// Layout [k/2][M] (A, transposed) and [k/2][N] (B).
// ---------------------------------------------------------------------------
__device__ float  g_h[NTOK * HDIM];
__device__ float  g_q[NTOK * KDIM];
__device__ float  g_k[NTOK * KDIM];
__device__ float  g_g[NTOK * KDIM];
__device__ float  g_v[NTOK * VDIM];
__device__ float  g_attn[NTOK * VDIM];
__device__ float2 g_asplit[(HDIM / 2) * NTOK];    // 16 MB
__device__ float2 g_bsplit[(HDIM / 2) * VOCAB];   // 131 MB (max = head)

// ---------------------------------------------------------------------------
// Helpers
// ---------------------------------------------------------------------------
__device__ __forceinline__ uint32_t smem_u32(const void* p) {
    uint32_t a;
    asm("{ .reg .u64 t; cvta.to.shared.u64 t, %1; cvt.u32.u64 %0, t; }"
        : "=r"(a) : "l"(p));
    return a;
}

__device__ __forceinline__ void cp_async16(uint32_t dst, const void* src) {
    asm volatile("cp.async.cg.shared.global [%0], [%1], 16;"
                 :: "r"(dst), "l"(src));
}
#define CP_COMMIT() asm volatile("cp.async.commit_group;")
#define CP_WAIT(n)  asm volatile("cp.async.wait_group %0;" :: "n"(n))

// fp16 split of two consecutive k-values; lo scaled by 2048 so it stays in
// the fp16 NORMAL range (unscaled lo of 0.02-scale data is subnormal).
__device__ __forceinline__ float2 split16(float v0, float v1) {
    __half h0 = __float2half_rn(v0), h1 = __float2half_rn(v1);
    __half l0 = __float2half_rn((v0 - __half2float(h0)) * LO_SCALE);
    __half l1 = __float2half_rn((v1 - __half2float(h1)) * LO_SCALE);
    __half2 hp = __halves2half2(h0, h1);
    __half2 lp = __halves2half2(l0, l1);
    float2 o;
    o.x = __uint_as_float(*reinterpret_cast<unsigned*>(&hp));
    o.y = __uint_as_float(*reinterpret_cast<unsigned*>(&lp));
    return o;
}

__device__ __forceinline__ void mma_f16(float c[4],
                                        unsigned a0, unsigned a1,
                                        unsigned a2, unsigned a3,
                                        unsigned b0, unsigned b1) {
    asm volatile(
        "mma.sync.aligned.m16n8k16.row.col.f32.f16.f16.f32 "
        "{%0,%1,%2,%3}, {%4,%5,%6,%7}, {%8,%9}, {%0,%1,%2,%3};"
        : "+f"(c[0]), "+f"(c[1]), "+f"(c[2]), "+f"(c[3])
        : "r"(a0), "r"(a1), "r"(a2), "r"(a3), "r"(b0), "r"(b1));
}

// ---------------------------------------------------------------------------
// Embedding gather
// ---------------------------------------------------------------------------
__global__ void embed_kernel(const int* __restrict__ ids,
                             const float* __restrict__ emb,
                             float* __restrict__ h)
{
    int tok = blockIdx.x;
    int id  = ids[tok];
    const float4* src = (const float4*)(emb + (size_t)id * HDIM);
    float4* dst       = (float4*)(h + (size_t)tok * HDIM);
    dst[threadIdx.x] = src[threadIdx.x];
}

// ---------------------------------------------------------------------------
// Pre-split: activations X[M,K] -> Y[k/2][M] (transpose + fp16 hi/lo pairs)
// ---------------------------------------------------------------------------
__global__ void split_a_kernel(const float* __restrict__ X,
                               float2* __restrict__ Y, int M, int K)
{
    __shared__ float t[32][33];
    int k0 = blockIdx.x * 32, m0 = blockIdx.y * 32;
    int tx = threadIdx.x, ty = threadIdx.y;   // block (32, 8)
    #pragma unroll
    for (int j = 0; j < 4; j++)
        t[ty + 8 * j][tx] = X[(size_t)(m0 + ty + 8 * j) * K + k0 + tx];
    __syncthreads();
    #pragma unroll
    for (int j = 0; j < 2; j++) {
        int pi = ty + 8 * j;                  // k-pair index 0..15
        float v0 = t[tx][2 * pi];             // m = m0+tx, k = k0+2pi
        float v1 = t[tx][2 * pi + 1];
        Y[(size_t)(k0 / 2 + pi) * M + m0 + tx] = split16(v0, v1);
    }
}

// Weights W[K,N] -> Y[k/2][N]
__global__ void split_b_kernel(const float* __restrict__ W,
                               float2* __restrict__ Y, int KH, int N)
{
    int i = blockIdx.x * 256 + threadIdx.x;
    if (i < KH * N) {
        int kp = i / N, n = i - kp * N;
        float v0 = W[(size_t)(2 * kp) * N + n];
        float v1 = W[(size_t)(2 * kp + 1) * N + n];
        Y[i] = split16(v0, v1);
    }
}

// ---------------------------------------------------------------------------
// FP16 mma.sync GEMM, 3-term split with scaled-lo dual accumulators:
//   C = (acc_hi + acc_lo/2048) + bias   (opt sigmoid)
// CTA tile 128x128; 512 threads, 16 warps (4x4), warp tile 32x32 =
// 2x4 m16n8k16 tiles -> ~120 regs/thread -> 16 warps/SM (2x the latency
// hiding of the 256-thr/64x32 version that measured tensor=35%).
// k-slab = 32 k (16 pair-rows); cp.async double buffer; SROW=132
// conflict-free smem rows (proven layout).
// ---------------------------------------------------------------------------
#define SROW   132
#define STILE  (16 * SROW)
#define SBUF   (2 * STILE)
#define GEMM_SMEM (2 * SBUF * 8)    // 67584 bytes

template<int ACT>
__global__ __launch_bounds__(512)
void tc_gemm(const float2* __restrict__ Ahl,
             const float2* __restrict__ Bhl,
             const float*  __restrict__ bias,
             float* __restrict__ C,
             int M, int N, int K)
{
    extern __shared__ float2 sm[];
    const int tid  = threadIdx.x;
    const int by   = blockIdx.x;        // M tile
    const int bx   = blockIdx.y;        // N tile
    const int warp = tid >> 5;          // 0..15
    const int lane = tid & 31;
    const int grp  = lane >> 2;         // 0..7
    const int tig  = lane & 3;          // 0..3
    const int wm   = (warp >> 2) * 32;  // warp M offset: 0/32/64/96
    const int wn   = (warp & 3) * 32;   // warp N offset: 0/32/64/96
    const int m0g  = by * 128;
    const int n0g  = bx * 128;

    const uint32_t sb = smem_u32(sm);

    float accH[2][4][4], accL[2][4][4];
    #pragma unroll
    for (int i = 0; i < 2; i++)
        #pragma unroll
        for (int j = 0; j < 4; j++)
            #pragma unroll
            for (int r = 0; r < 4; r++) { accH[i][j][r] = 0.0f; accL[i][j][r] = 0.0f; }

    // async copy one slab (16 pair-rows of A and B, 128 float2 each) into buf
    auto issue = [&](int kp0, int buf) {
        uint32_t ab = sb + (uint32_t)buf * (SBUF * 8);
        uint32_t bb = ab + STILE * 8;
        #pragma unroll
        for (int i = 0; i < 2; i++) {
            int c   = tid + i * 512;       // 0..1023
            int r   = c >> 6;              // pair-row 0..15
            int col = c & 63;              // 16B chunk (4 float2)
            cp_async16(ab + (uint32_t)r * (SROW * 8) + col * 16,
                       (const char*)(Ahl + (size_t)(kp0 + r) * M + m0g) + col * 16);
            cp_async16(bb + (uint32_t)r * (SROW * 8) + col * 16,
                       (const char*)(Bhl + (size_t)(kp0 + r) * N + n0g) + col * 16);
        }
    };

    issue(0, 0);
    CP_COMMIT();

    const int nIter = K >> 5;              // 32-k slabs
    for (int it = 0; it < nIter; it++) {
        const int buf = it & 1;
        if (it + 1 < nIter) {
            issue((it + 1) << 4, buf ^ 1);
            CP_COMMIT();
            CP_WAIT(1);
        } else {
            CP_WAIT(0);
        }
        __syncthreads();

        const float2* As = sm + buf * SBUF;
        const float2* Bs = As + STILE;

        #pragma unroll
        for (int ks = 0; ks < 2; ks++) {   // each ks = 8 pair-rows = k16
            const int kb = ks * 8;
            float2 af[2][4], bf[4][2];
            #pragma unroll
            for (int mt = 0; mt < 2; mt++) {
                int m0 = wm + mt * 16 + grp;
                af[mt][0] = As[(kb + tig) * SROW + m0];          // (grp,   kp tig)
                af[mt][1] = As[(kb + tig) * SROW + m0 + 8];      // (grp+8, kp tig)
                af[mt][2] = As[(kb + tig + 4) * SROW + m0];      // (grp,   kp tig+4)
                af[mt][3] = As[(kb + tig + 4) * SROW + m0 + 8];  // (grp+8, kp tig+4)
            }
            #pragma unroll
            for (int nt = 0; nt < 4; nt++) {
                int n0 = wn + nt * 8 + grp;
                bf[nt][0] = Bs[(kb + tig) * SROW + n0];          // (kp tig,   col)
                bf[nt][1] = Bs[(kb + tig + 4) * SROW + n0];      // (kp tig+4, col)
            }
            #pragma unroll
            for (int mt = 0; mt < 2; mt++)
                #pragma unroll
                for (int nt = 0; nt < 4; nt++) {
                    // hi*hi -> accH
                    mma_f16(accH[mt][nt],
                            __float_as_uint(af[mt][0].x), __float_as_uint(af[mt][1].x),
                            __float_as_uint(af[mt][2].x), __float_as_uint(af[mt][3].x),
                            __float_as_uint(bf[nt][0].x), __float_as_uint(bf[nt][1].x));
                    // lo'*hi -> accL
                    mma_f16(accL[mt][nt],
                            __float_as_uint(af[mt][0].y), __float_as_uint(af[mt][1].y),
                            __float_as_uint(af[mt][2].y), __float_as_uint(af[mt][3].y),
                            __float_as_uint(bf[nt][0].x), __float_as_uint(bf[nt][1].x));
                    // hi*lo' -> accL
                    mma_f16(accL[mt][nt],
                            __float_as_uint(af[mt][0].x), __float_as_uint(af[mt][1].x),
                            __float_as_uint(af[mt][2].x), __float_as_uint(af[mt][3].x),
                            __float_as_uint(bf[nt][0].y), __float_as_uint(bf[nt][1].y));
                }
        }
        __syncthreads();
    }

    // epilogue: C = accH + accL/2048 + bias
    #pragma unroll
    for (int nt = 0; nt < 4; nt++) {
        int col = n0g + wn + nt * 8 + tig * 2;
        float2 bs = *(const float2*)(bias + col);
        #pragma unroll
        for (int mt = 0; mt < 2; mt++) {
            int row0 = m0g + wm + mt * 16 + grp;
            float v0 = fmaf(accL[mt][nt][0], LO_INV, accH[mt][nt][0]) + bs.x;
            float v1 = fmaf(accL[mt][nt][1], LO_INV, accH[mt][nt][1]) + bs.y;
            float v2 = fmaf(accL[mt][nt][2], LO_INV, accH[mt][nt][2]) + bs.x;
            float v3 = fmaf(accL[mt][nt][3], LO_INV, accH[mt][nt][3]) + bs.y;
            if (ACT == 1) {
                v0 = 1.0f / (1.0f + __expf(-v0));
                v1 = 1.0f / (1.0f + __expf(-v1));
                v2 = 1.0f / (1.0f + __expf(-v2));
                v3 = 1.0f / (1.0f + __expf(-v3));
            }
            *(float2*)(C + (size_t)row0 * N + col)       = make_float2(v0, v1);
            *(float2*)(C + (size_t)(row0 + 8) * N + col) = make_float2(v2, v3);
        }
    }
}

// ---------------------------------------------------------------------------
// Gated linear-attention scan (register-resident state; unchanged)
// ---------------------------------------------------------------------------
__global__ __launch_bounds__(256)
void scan_kernel(const float* __restrict__ q,
                 const float* __restrict__ kk,
                 const float* __restrict__ gg,
                 const float* __restrict__ vv,
                 float* __restrict__ attn)
{
    const int b    = blockIdx.x >> 5;
    const int vblk = blockIdx.x & 31;
    const int v0   = vblk * 32;
    const int warp = threadIdx.x >> 5;
    const int lane = threadIdx.x & 31;
    const int myv  = v0 + warp * 4;

    __shared__ float sq[KDIM];
    __shared__ float sk[KDIM];
    __shared__ float sg[KDIM];
    __shared__ float sv[32];

    float s[16][4];
    #pragma unroll
    for (int i = 0; i < 16; i++)
        #pragma unroll
        for (int j = 0; j < 4; j++) s[i][j] = 0.0f;

    const float* qb = q  + (size_t)b * TSEQ * KDIM;
    const float* kb = kk + (size_t)b * TSEQ * KDIM;
    const float* gb = gg + (size_t)b * TSEQ * KDIM;
    const float* vb = vv + (size_t)b * TSEQ * VDIM;

    for (int t = 0; t < TSEQ; t++) {
        const float* qt = qb + (size_t)t * KDIM;
        const float* kt = kb + (size_t)t * KDIM;
        const float* gt = gb + (size_t)t * KDIM;
        #pragma unroll
        for (int i = threadIdx.x; i < KDIM; i += 256) {
            sq[i] = qt[i];
            sk[i] = kt[i];
            sg[i] = gt[i];
        }
        if (threadIdx.x < 32)
            sv[threadIdx.x] = vb[(size_t)t * VDIM + v0 + threadIdx.x];
        __syncthreads();

        float vr0 = sv[warp * 4 + 0];
        float vr1 = sv[warp * 4 + 1];
        float vr2 = sv[warp * 4 + 2];
        float vr3 = sv[warp * 4 + 3];

        float a0 = 0.f, a1 = 0.f, a2 = 0.f, a3 = 0.f;
        #pragma unroll
        for (int i = 0; i < 16; i++) {
            int kidx = i * 32 + lane;
            float qv = sq[kidx];
            float kv = sk[kidx];
            float gv = sg[kidx];
            s[i][0] = s[i][0] * gv + kv * vr0;  a0 += s[i][0] * qv;
            s[i][1] = s[i][1] * gv + kv * vr1;  a1 += s[i][1] * qv;
            s[i][2] = s[i][2] * gv + kv * vr2;  a2 += s[i][2] * qv;
            s[i][3] = s[i][3] * gv + kv * vr3;  a3 += s[i][3] * qv;
        }

        #pragma unroll
        for (int off = 16; off > 0; off >>= 1) {
            a0 += __shfl_xor_sync(0xffffffffu, a0, off);
            a1 += __shfl_xor_sync(0xffffffffu, a1, off);
            a2 += __shfl_xor_sync(0xffffffffu, a2, off);
            a3 += __shfl_xor_sync(0xffffffffu, a3, off);
        }
        if (lane == 0) {
            *(float4*)&attn[((size_t)(b * TSEQ + t)) * VDIM + myv] =
                make_float4(a0, a1, a2, a3);
        }
        __syncthreads();
    }
}

// ---------------------------------------------------------------------------
// Launch
// ---------------------------------------------------------------------------
extern "C" void kernel_launch(void* const* d_in, const int* in_sizes, int n_in,
                              void* d_out, int out_size)
{
    const int*   ids    = (const int*)  d_in[0];
    const float* emb    = (const float*)d_in[1];
    const float* Wq     = (const float*)d_in[2];
    const float* bq     = (const float*)d_in[3];
    const float* Wk     = (const float*)d_in[4];
    const float* bk     = (const float*)d_in[5];
    const float* Wg     = (const float*)d_in[6];
    const float* bg     = (const float*)d_in[7];
    const float* Wv     = (const float*)d_in[8];
    const float* bv     = (const float*)d_in[9];
    const float* Wo     = (const float*)d_in[10];
    const float* bo     = (const float*)d_in[11];
    const float* W_head = (const float*)d_in[12];
    const float* b_head = (const float*)d_in[13];
    float* out = (float*)d_out;

    void* p;
    float  *P_H, *P_Q, *P_K, *P_G, *P_V, *P_A;
    float2 *P_AS, *P_BS;
    cudaGetSymbolAddress(&p, g_h);      P_H  = (float*)p;
    cudaGetSymbolAddress(&p, g_q);      P_Q  = (float*)p;
    cudaGetSymbolAddress(&p, g_k);      P_K  = (float*)p;
    cudaGetSymbolAddress(&p, g_g);      P_G  = (float*)p;
    cudaGetSymbolAddress(&p, g_v);      P_V  = (float*)p;
    cudaGetSymbolAddress(&p, g_attn);   P_A  = (float*)p;
    cudaGetSymbolAddress(&p, g_asplit); P_AS = (float2*)p;
    cudaGetSymbolAddress(&p, g_bsplit); P_BS = (float2*)p;

    cudaFuncSetAttribute(tc_gemm<0>,
                         cudaFuncAttributeMaxDynamicSharedMemorySize, GEMM_SMEM);
    cudaFuncSetAttribute(tc_gemm<1>,
                         cudaFuncAttributeMaxDynamicSharedMemorySize, GEMM_SMEM);

    // 1) Embedding gather
    embed_kernel<<<NTOK, 256>>>(ids, emb, P_H);

    dim3 tb(32, 8);
    dim3 gaT(HDIM / 32, NTOK / 32);
    dim3 gK(NTOK / 128, KDIM / 128);           // (32, 4)
    dim3 gV(NTOK / 128, VDIM / 128);           // (32, 8)

    const int nbK = ((HDIM / 2) * KDIM + 255) / 256;
    const int nbV = ((HDIM / 2) * VDIM + 255) / 256;
    const int nbO = ((VDIM / 2) * ODIM + 255) / 256;

    // 2) Layers
    for (int l = 0; l < NLAYER; l++) {
        const float* wq = Wq + (size_t)l * HDIM * KDIM;
        const float* wk = Wk + (size_t)l * HDIM * KDIM;
        const float* wg = Wg + (size_t)l * HDIM * KDIM;
        const float* wv = Wv + (size_t)l * HDIM * VDIM;
        const float* wo = Wo + (size_t)l * VDIM * ODIM;

        split_a_kernel<<<gaT, tb>>>(P_H, P_AS, NTOK, HDIM);

        split_b_kernel<<<nbK, 256>>>(wq, P_BS, HDIM / 2, KDIM);
        tc_gemm<0><<<gK, 512, GEMM_SMEM>>>(P_AS, P_BS, bq + (size_t)l * KDIM,
                                           P_Q, NTOK, KDIM, HDIM);
        split_b_kernel<<<nbK, 256>>>(wk, P_BS, HDIM / 2, KDIM);
        tc_gemm<1><<<gK, 512, GEMM_SMEM>>>(P_AS, P_BS, bk + (size_t)l * KDIM,
                                           P_K, NTOK, KDIM, HDIM);
        split_b_kernel<<<nbK, 256>>>(wg, P_BS, HDIM / 2, KDIM);
        tc_gemm<1><<<gK, 512, GEMM_SMEM>>>(P_AS, P_BS, bg + (size_t)l * KDIM,
                                           P_G, NTOK, KDIM, HDIM);
        split_b_kernel<<<nbV, 256>>>(wv, P_BS, HDIM / 2, VDIM);
        tc_gemm<0><<<gV, 512, GEMM_SMEM>>>(P_AS, P_BS, bv + (size_t)l * VDIM,
                                           P_V, NTOK, VDIM, HDIM);

        scan_kernel<<<128, 256>>>(P_Q, P_K, P_G, P_V, P_A);

        split_a_kernel<<<gaT, tb>>>(P_A, P_AS, NTOK, VDIM);
        split_b_kernel<<<nbO, 256>>>(wo, P_BS, VDIM / 2, ODIM);
        tc_gemm<0><<<gV, 512, GEMM_SMEM>>>(P_AS, P_BS, bo + (size_t)l * ODIM,
                                           P_H, NTOK, ODIM, VDIM);
    }

    // 3) Head
    split_a_kernel<<<gaT, tb>>>(P_H, P_AS, NTOK, HDIM);
    const int nbH = ((HDIM / 2) * VOCAB + 255) / 256;
    split_b_kernel<<<nbH, 256>>>(W_head, P_BS, HDIM / 2, VOCAB);
    dim3 gH(NTOK / 128, VOCAB / 128);          // (32, 250)
    tc_gemm<0><<<gH, 512, GEMM_SMEM>>>(P_AS, P_BS, b_head, out,
                                       NTOK, VOCAB, HDIM);
}